// round 13
// baseline (speedup 1.0000x reference)
#include <cuda_runtime.h>
#include <cuda_bf16.h>
#include <math_constants.h>
#include <cstdint>

#define CIN   384
#define COUT  192
#define NB    4
#define NPER  4096
#define MPER  16384
#define NTOT  (NB * NPER)   // 16384
#define MTOT  (NB * MPER)   // 65536
#define LN_EPS 1e-5f

#define GRID_R 8
#define NCELL  (GRID_R * GRID_R * GRID_R)   // 512
#define TCELL  (NB * NCELL)                 // 2048
#define CELL_H (1.0f / GRID_R)

typedef unsigned long long ull;

// ------------------------- static device scratch ---------------------------
__device__ float  g_h [(size_t)NTOT * COUT];
__device__ float  g_wk[(size_t)MTOT * 3];
__device__ int    g_ik[(size_t)MTOT * 3];
__device__ int    g_cnt[TCELL];
__device__ int    g_cellstart[TCELL + 1];
__device__ int    g_fill[TCELL];
__device__ float4 g_pts4[NTOT];
// w^T split to bf16 hi/lo, [n][k] row-major
__device__ __nv_bfloat16 g_w2h[(size_t)COUT * CIN];
__device__ __nv_bfloat16 g_w2l[(size_t)COUT * CIN];
__device__ __nv_bfloat16 g_w1h[(size_t)COUT * COUT];
__device__ __nv_bfloat16 g_w1l[(size_t)COUT * COUT];

// ------------------------- helpers -----------------------------------------
__device__ __forceinline__ float warp_sum(float v) {
#pragma unroll
    for (int o = 16; o > 0; o >>= 1) v += __shfl_xor_sync(0xffffffffu, v, o);
    return v;
}
__device__ __forceinline__ uint32_t smem_u32(const void* p) {
    uint32_t a;
    asm("{ .reg .u64 t; cvta.to.shared.u64 t, %1; cvt.u32.u64 %0, t; }" : "=r"(a) : "l"(p));
    return a;
}
#define LDSM4(r, addr)                                                          \
    asm volatile("ldmatrix.sync.aligned.m8n8.x4.shared.b16 {%0,%1,%2,%3}, [%4];"\
        : "=r"((r)[0]), "=r"((r)[1]), "=r"((r)[2]), "=r"((r)[3]) : "r"(addr))
#define MMA_BF16(c, a, b0, b1)                                                  \
    asm volatile("mma.sync.aligned.m16n8k16.row.col.f32.bf16.bf16.f32 "         \
        "{%0,%1,%2,%3}, {%4,%5,%6,%7}, {%8,%9}, {%0,%1,%2,%3};"                 \
        : "+f"((c)[0]), "+f"((c)[1]), "+f"((c)[2]), "+f"((c)[3])                \
        : "r"((a)[0]), "r"((a)[1]), "r"((a)[2]), "r"((a)[3]), "r"(b0), "r"(b1))

__device__ __forceinline__ int cell1(float v) {
    int c = (int)(v * GRID_R);
    return min(GRID_R - 1, max(0, c));
}
__device__ __forceinline__ void ins3(float s, int gi,
                                     float& s0, float& s1, float& s2,
                                     int& i0, int& i1, int& i2) {
    if (s < s2) {
        if (s < s1) {
            s2 = s1; i2 = i1;
            if (s < s0) { s1 = s0; i1 = i0; s0 = s; i0 = gi; }
            else        { s1 = s;  i1 = gi; }
        } else { s2 = s; i2 = gi; }
    }
}
__device__ __forceinline__ void scan_run(int lo, int hi,
                                         float qx, float qy, float qz,
                                         float& s0, float& s1, float& s2,
                                         int& i0, int& i1, int& i2) {
    int j = lo;
    for (; j + 4 <= hi; j += 4) {
        const float4 p0 = g_pts4[j];
        const float4 p1 = g_pts4[j + 1];
        const float4 p2 = g_pts4[j + 2];
        const float4 p3 = g_pts4[j + 3];
        float dx, dy, dz;
        dx = qx - p0.x; dy = qy - p0.y; dz = qz - p0.z;
        const float a0 = fmaf(dx, dx, fmaf(dy, dy, dz * dz));
        dx = qx - p1.x; dy = qy - p1.y; dz = qz - p1.z;
        const float a1 = fmaf(dx, dx, fmaf(dy, dy, dz * dz));
        dx = qx - p2.x; dy = qy - p2.y; dz = qz - p2.z;
        const float a2 = fmaf(dx, dx, fmaf(dy, dy, dz * dz));
        dx = qx - p3.x; dy = qy - p3.y; dz = qz - p3.z;
        const float a3 = fmaf(dx, dx, fmaf(dy, dy, dz * dz));
        ins3(a0, __float_as_int(p0.w), s0, s1, s2, i0, i1, i2);
        ins3(a1, __float_as_int(p1.w), s0, s1, s2, i0, i1, i2);
        ins3(a2, __float_as_int(p2.w), s0, s1, s2, i0, i1, i2);
        ins3(a3, __float_as_int(p3.w), s0, s1, s2, i0, i1, i2);
    }
    for (; j < hi; j++) {
        const float4 p = g_pts4[j];
        const float dx = qx - p.x, dy = qy - p.y, dz = qz - p.z;
        const float s = fmaf(dx, dx, fmaf(dy, dy, dz * dz));
        ins3(s, __float_as_int(p.w), s0, s1, s2, i0, i1, i2);
    }
}

// ------------------------- grid build --------------------------------------
__global__ void k_grid_zero() {
    int i = blockIdx.x * 1024 + threadIdx.x;
    if (i < TCELL) g_cnt[i] = 0;
}
__global__ __launch_bounds__(256) void k_grid_count(const float* __restrict__ xyz) {
    int i = blockIdx.x * 256 + threadIdx.x;
    int b = i >> 12;
    int cx = cell1(xyz[i * 3 + 0]);
    int cy = cell1(xyz[i * 3 + 1]);
    int cz = cell1(xyz[i * 3 + 2]);
    atomicAdd(&g_cnt[b * NCELL + (cz * GRID_R + cy) * GRID_R + cx], 1);
}
__global__ __launch_bounds__(1024) void k_grid_scan() {
    __shared__ int A[TCELL], B[TCELL];
    int t = threadIdx.x;
    A[t] = g_cnt[t];  A[t + 1024] = g_cnt[t + 1024];
    __syncthreads();
    int* src = A; int* dst = B;
    for (int off = 1; off < TCELL; off <<= 1) {
        dst[t]        = src[t]        + (t        >= off ? src[t        - off] : 0);
        dst[t + 1024] = src[t + 1024] + (t + 1024 >= off ? src[t + 1024 - off] : 0);
        __syncthreads();
        int* tmp = src; src = dst; dst = tmp;
    }
    int ex0 = (t == 0) ? 0 : src[t - 1];
    g_cellstart[t] = ex0;  g_fill[t] = ex0;
    int u = t + 1024;
    int ex1 = src[u - 1];
    g_cellstart[u] = ex1;  g_fill[u] = ex1;
    if (t == 0) g_cellstart[TCELL] = NTOT;
}
__global__ __launch_bounds__(256) void k_grid_scatter(const float* __restrict__ xyz) {
    int i = blockIdx.x * 256 + threadIdx.x;
    int b = i >> 12;
    float x = xyz[i * 3 + 0], y = xyz[i * 3 + 1], z = xyz[i * 3 + 2];
    int cid = b * NCELL + (cell1(z) * GRID_R + cell1(y)) * GRID_R + cell1(x);
    int pos = atomicAdd(&g_fill[cid], 1);
    g_pts4[pos] = make_float4(x, y, z, __int_as_float(i));
}

// ------------------------- weight prep: w[k][n] -> wt[n][k], bf16 hi/lo -----
__global__ __launch_bounds__(256) void k_prep_w(const float* __restrict__ w,
                                                int K, int which) {
    int i = blockIdx.x * 256 + threadIdx.x;
    if (i >= K * COUT) return;
    int k = i / COUT, n = i % COUT;
    float v = w[i];
    __nv_bfloat16 h = __float2bfloat16(v);
    __nv_bfloat16 l = __float2bfloat16(v - __bfloat162float(h));
    size_t o = (size_t)n * K + k;
    if (which == 0) { g_w2h[o] = h; g_w2l[o] = l; }
    else            { g_w1h[o] = h; g_w1l[o] = l; }
}

// ------------------------- grid 3-NN ---------------------------------------
__global__ __launch_bounds__(256) void k_knn_grid(const float* __restrict__ sxyz) {
    const int q = blockIdx.x * 256 + threadIdx.x;
    const int b = q >> 14;
    const float qx = sxyz[q * 3 + 0];
    const float qy = sxyz[q * 3 + 1];
    const float qz = sxyz[q * 3 + 2];
    const int cx = cell1(qx), cy = cell1(qy), cz = cell1(qz);
    const int base = b * NCELL;

    float s0 = CUDART_INF_F, s1 = CUDART_INF_F, s2 = CUDART_INF_F;
    int   i0 = 0, i1 = 0, i2 = 0;

    {
        const int zl = max(0, cz - 1), zh = min(GRID_R - 1, cz + 1);
        const int yl = max(0, cy - 1), yh = min(GRID_R - 1, cy + 1);
        const int xl = max(0, cx - 1), xh = min(GRID_R - 1, cx + 1);
        for (int Z = zl; Z <= zh; Z++)
            for (int Y = yl; Y <= yh; Y++) {
                const int rowb = base + (Z * GRID_R + Y) * GRID_R;
                const int lo = g_cellstart[rowb + xl];
                const int hi = g_cellstart[rowb + xh + 1];
                scan_run(lo, hi, qx, qy, qz, s0, s1, s2, i0, i1, i2);
            }
    }
    float rc = CUDART_INF_F;
    if (cx - 1 > 0)          rc = fminf(rc, qx - (cx - 1) * CELL_H);
    if (cx + 1 < GRID_R - 1) rc = fminf(rc, (cx + 2) * CELL_H - qx);
    if (cy - 1 > 0)          rc = fminf(rc, qy - (cy - 1) * CELL_H);
    if (cy + 1 < GRID_R - 1) rc = fminf(rc, (cy + 2) * CELL_H - qy);
    if (cz - 1 > 0)          rc = fminf(rc, qz - (cz - 1) * CELL_H);
    if (cz + 1 < GRID_R - 1) rc = fminf(rc, (cz + 2) * CELL_H - qz);

    if (!(s2 < rc * rc)) {
        bool done = false;
        for (int R = 2; R < GRID_R && !done; R++) {
            const int zl = max(0, cz - R), zh = min(GRID_R - 1, cz + R);
            const int yl = max(0, cy - R), yh = min(GRID_R - 1, cy + R);
            const int xl = max(0, cx - R), xh = min(GRID_R - 1, cx + R);
            for (int Z = zl; Z <= zh; Z++) {
                const bool zedge = (Z == cz - R) || (Z == cz + R);
                for (int Y = yl; Y <= yh; Y++) {
                    const bool yedge = (Y == cy - R) || (Y == cy + R);
                    const int rowb = base + (Z * GRID_R + Y) * GRID_R;
                    if (zedge || yedge) {
                        const int lo = g_cellstart[rowb + xl];
                        const int hi = g_cellstart[rowb + xh + 1];
                        scan_run(lo, hi, qx, qy, qz, s0, s1, s2, i0, i1, i2);
                    } else {
#pragma unroll
                        for (int e = 0; e < 2; e++) {
                            const int X = (e == 0) ? (cx - R) : (cx + R);
                            if (X < 0 || X >= GRID_R) continue;
                            const int lo = g_cellstart[rowb + X];
                            const int hi = g_cellstart[rowb + X + 1];
                            scan_run(lo, hi, qx, qy, qz, s0, s1, s2, i0, i1, i2);
                        }
                    }
                }
            }
            float rcv = CUDART_INF_F;
            if (cx - R > 0)          rcv = fminf(rcv, qx - (cx - R) * CELL_H);
            if (cx + R < GRID_R - 1) rcv = fminf(rcv, (cx + R + 1) * CELL_H - qx);
            if (cy - R > 0)          rcv = fminf(rcv, qy - (cy - R) * CELL_H);
            if (cy + R < GRID_R - 1) rcv = fminf(rcv, (cy + R + 1) * CELL_H - qy);
            if (cz - R > 0)          rcv = fminf(rcv, qz - (cz - R) * CELL_H);
            if (cz + R < GRID_R - 1) rcv = fminf(rcv, (cz + R + 1) * CELL_H - qz);
            if (s2 < rcv * rcv) done = true;
        }
    }

    const float d0 = sqrtf(fmaxf(s0, 0.f));
    const float d1 = sqrtf(fmaxf(s1, 0.f));
    const float d2 = sqrtf(fmaxf(s2, 0.f));
    const float r0 = 1.0f / (d0 + 1e-8f);
    const float r1 = 1.0f / (d1 + 1e-8f);
    const float r2 = 1.0f / (d2 + 1e-8f);
    const float rs = 1.0f / (r0 + r1 + r2);
    g_wk[q * 3 + 0] = r0 * rs;  g_ik[q * 3 + 0] = i0;
    g_wk[q * 3 + 1] = r1 * rs;  g_ik[q * 3 + 1] = i1;
    g_wk[q * 3 + 2] = r2 * rs;  g_ik[q * 3 + 2] = i2;
}

// ---------------------------------------------------------------------------
// HMMA LN+GEMM: dst = LN(x) @ W + bias (+ optional 3-NN gather add)
// CTA: 256 threads (8 warps), M tile 64, N = 192, K chunked by 64.
// bf16 split: acc += xh*wh + xl*wh + xh*wl  (fp32 accumulators in mma)
// ---------------------------------------------------------------------------
template<int KDIM, bool GATHER>
__global__ __launch_bounds__(256) void k_ln_gemm_mma(
    const float* __restrict__ xin,
    const float* __restrict__ ln_g, const float* __restrict__ ln_b,
    const float* __restrict__ bias,
    float* __restrict__ outp)
{
    extern __shared__ __align__(16) char smem[];
    constexpr int APITCH = KDIM * 2;                 // bytes per A row
    constexpr uint32_t OFF_ALO  = 64 * APITCH;
    constexpr uint32_t OFF_BH   = 2 * 64 * APITCH;
    constexpr uint32_t OFF_BL   = OFF_BH + 192 * 64 * 2;
    constexpr uint32_t OFF_BIAS = OFF_BL + 192 * 64 * 2;
    constexpr uint32_t OFF_SW   = OFF_BIAS + 192 * 4;
    constexpr uint32_t OFF_SI   = OFF_SW + 64 * 3 * 4;

    const uint32_t sb = smem_u32(smem);
    const int tid = threadIdx.x, wid = tid >> 5, lane = tid & 31;
    const int row0 = blockIdx.x * 64;

    const __nv_bfloat16* wh = (KDIM == CIN) ? g_w2h : g_w1h;
    const __nv_bfloat16* wl = (KDIM == CIN) ? g_w2l : g_w1l;

    float* s_bias = (float*)(smem + OFF_BIAS);
    for (int i = tid; i < 192; i += 256) s_bias[i] = bias[i];
    if (GATHER) {
        float* ssw = (float*)(smem + OFF_SW);
        int*   ssi = (int*)(smem + OFF_SI);
        if (tid < 64) {
#pragma unroll
            for (int c = 0; c < 3; c++) {
                ssw[tid * 3 + c] = g_wk[(row0 + tid) * 3 + c];
                ssi[tid * 3 + c] = g_ik[(row0 + tid) * 3 + c];
            }
        }
    }

    // ----- LayerNorm + bf16 hi/lo split into swizzled smem -----
    for (int rr = 0; rr < 8; rr++) {
        const int r = wid * 8 + rr;
        const float* x = xin + (size_t)(row0 + r) * KDIM;
        float s = 0.f, ss = 0.f;
        for (int f = lane; f < KDIM / 4; f += 32) {
            const float4 v = *reinterpret_cast<const float4*>(x + 4 * f);
            s  += v.x + v.y + v.z + v.w;
            ss += v.x * v.x + v.y * v.y + v.z * v.z + v.w * v.w;
        }
        s  = warp_sum(s);
        ss = warp_sum(ss);
        const float mu  = s * (1.0f / KDIM);
        const float inv = rsqrtf(ss * (1.0f / KDIM) - mu * mu + LN_EPS);
        for (int c = lane; c < KDIM / 8; c += 32) {
            const float4 va = *reinterpret_cast<const float4*>(x + 8 * c);
            const float4 vb = *reinterpret_cast<const float4*>(x + 8 * c + 4);
            const float v[8] = {va.x, va.y, va.z, va.w, vb.x, vb.y, vb.z, vb.w};
            uint32_t hp[4], lp[4];
#pragma unroll
            for (int t = 0; t < 4; t++) {
                const int k0 = 8 * c + 2 * t;
                const float n0 = (v[2*t]   - mu) * inv * ln_g[k0]     + ln_b[k0];
                const float n1 = (v[2*t+1] - mu) * inv * ln_g[k0 + 1] + ln_b[k0 + 1];
                const __nv_bfloat162 h2 = __floats2bfloat162_rn(n0, n1);
                const float r0 = n0 - __bfloat162float(__low2bfloat16(h2));
                const float r1 = n1 - __bfloat162float(__high2bfloat16(h2));
                const __nv_bfloat162 l2 = __floats2bfloat162_rn(r0, r1);
                hp[t] = *(const uint32_t*)&h2;
                lp[t] = *(const uint32_t*)&l2;
            }
            const uint32_t off = (uint32_t)r * APITCH + ((uint32_t)(c ^ (r & 7)) << 4);
            *(uint4*)(smem + off)           = make_uint4(hp[0], hp[1], hp[2], hp[3]);
            *(uint4*)(smem + OFF_ALO + off) = make_uint4(lp[0], lp[1], lp[2], lp[3]);
        }
    }

    // ----- mainloop -----
    const int wm = wid & 1;          // 2 row-halves of 32
    const int wn = wid >> 1;         // 4 col-quarters of 48
    float acc[2][6][4];
#pragma unroll
    for (int mt = 0; mt < 2; mt++)
#pragma unroll
        for (int nt = 0; nt < 6; nt++)
#pragma unroll
            for (int e = 0; e < 4; e++) acc[mt][nt][e] = 0.f;

    const int rowAb = wm * 32 + (lane & 15);
    const int kAoff = (lane >> 4) << 3;          // 0 or 8
    const int rowBl = (lane & 7) + ((lane >> 4) << 3);
    const int cBoff = (lane >> 3) & 1;           // 0 or 1 (8-k units)

    for (int kc = 0; kc < KDIM / 64; kc++) {
        __syncthreads();
        // copy B chunk (hi + lo) with swizzle
        for (int u = tid; u < 192 * 8; u += 256) {
            const int n = u >> 3, c = u & 7;
            const uint32_t dsto = (uint32_t)n * 128 + ((uint32_t)(c ^ (n & 7)) << 4);
            const size_t srco = (size_t)n * KDIM + kc * 64 + c * 8;
            *(uint4*)(smem + OFF_BH + dsto) = *(const uint4*)(wh + srco);
            *(uint4*)(smem + OFF_BL + dsto) = *(const uint4*)(wl + srco);
        }
        __syncthreads();

#pragma unroll
        for (int ks = 0; ks < 4; ks++) {
            const int kg = kc * 64 + ks * 16;
            uint32_t ah[2][4], al[2][4], bh[3][4], bl[3][4];
#pragma unroll
            for (int mt = 0; mt < 2; mt++) {
                const uint32_t ra = rowAb + mt * 16;
                const uint32_t c = (uint32_t)((kg + kAoff) >> 3);
                const uint32_t off = ra * APITCH + ((c ^ (ra & 7)) << 4);
                LDSM4(ah[mt], sb + off);
                LDSM4(al[mt], sb + OFF_ALO + off);
            }
#pragma unroll
            for (int ng = 0; ng < 3; ng++) {
                const uint32_t rb = (uint32_t)(wn * 48 + ng * 16 + rowBl);
                const uint32_t c = (uint32_t)((ks * 2) + cBoff);
                const uint32_t off = rb * 128 + ((c ^ (rb & 7)) << 4);
                LDSM4(bh[ng], sb + OFF_BH + off);
                LDSM4(bl[ng], sb + OFF_BL + off);
            }
#pragma unroll
            for (int mt = 0; mt < 2; mt++)
#pragma unroll
                for (int nt = 0; nt < 6; nt++) {
                    const int ng = nt >> 1, hf = (nt & 1) * 2;
                    MMA_BF16(acc[mt][nt], ah[mt], bh[ng][hf], bh[ng][hf + 1]);
                    MMA_BF16(acc[mt][nt], al[mt], bh[ng][hf], bh[ng][hf + 1]);
                    MMA_BF16(acc[mt][nt], ah[mt], bl[ng][hf], bl[ng][hf + 1]);
                }
        }
    }

    // ----- epilogue: fragments -> gmem (bias + optional gather) -----
    float* dst = GATHER ? outp : g_h;
    const float* ssw = (const float*)(smem + OFF_SW);
    const int*   ssi = (const int*)(smem + OFF_SI);
    const int quad = lane >> 2, qt = lane & 3;
#pragma unroll
    for (int mt = 0; mt < 2; mt++) {
#pragma unroll
        for (int nt = 0; nt < 6; nt++) {
            const int n = wn * 48 + nt * 8 + qt * 2;
            const float bx = s_bias[n], by = s_bias[n + 1];
            float v00 = acc[mt][nt][0] + bx, v01 = acc[mt][nt][1] + by;
            float v10 = acc[mt][nt][2] + bx, v11 = acc[mt][nt][3] + by;
            const int m0 = wm * 32 + mt * 16 + quad;
            const int m1 = m0 + 8;
            if (GATHER) {
#pragma unroll
                for (int nn = 0; nn < 3; nn++) {
                    const float w0 = ssw[m0 * 3 + nn];
                    const float2 h0 = *(const float2*)(g_h + (size_t)ssi[m0 * 3 + nn] * COUT + n);
                    v00 = fmaf(w0, h0.x, v00);  v01 = fmaf(w0, h0.y, v01);
                    const float w1n = ssw[m1 * 3 + nn];
                    const float2 h1 = *(const float2*)(g_h + (size_t)ssi[m1 * 3 + nn] * COUT + n);
                    v10 = fmaf(w1n, h1.x, v10); v11 = fmaf(w1n, h1.y, v11);
                }
            }
            *(float2*)(dst + (size_t)(row0 + m0) * COUT + n) = make_float2(v00, v01);
            *(float2*)(dst + (size_t)(row0 + m1) * COUT + n) = make_float2(v10, v11);
        }
    }
}

// ---------------------------------------------------------------------------
__global__ void k_tail_fast(const float* __restrict__ sxyz,
                            const int* __restrict__ soff,
                            float* __restrict__ out)
{
    const int i = blockIdx.x * blockDim.x + threadIdx.x;
    const int n4 = MTOT * 3 / 4;
    const size_t base = (size_t)MTOT * COUT;
    if (i < n4) {
        ((float4*)(out + base))[i] = ((const float4*)sxyz)[i];
    } else if (i - n4 < NB) {
        out[base + (size_t)MTOT * 3 + (i - n4)] = (float)soff[i - n4];
    }
}
__global__ void k_tail_scalar(const float* __restrict__ sxyz,
                              const int* __restrict__ soff,
                              float* __restrict__ out, int extra)
{
    const int i = blockIdx.x * blockDim.x + threadIdx.x;
    if (i >= extra) return;
    const size_t base = (size_t)MTOT * COUT;
    if (i < MTOT * 3) out[base + i] = sxyz[i];
    else if (i - MTOT * 3 < NB) out[base + i] = (float)soff[i - MTOT * 3];
}

// ---------------------------------------------------------------------------
extern "C" void kernel_launch(void* const* d_in, const int* in_sizes, int n_in,
                              void* d_out, int out_size)
{
    const float* feats  = (const float*)d_in[0];
    const float* xyz    = (const float*)d_in[1];
    const float* sxyz   = (const float*)d_in[2];
    const float* sfeats = (const float*)d_in[3];
    const int*   soff   = (const int*)  d_in[5];
    const float* ln1_g  = (const float*)d_in[6];
    const float* ln1_b  = (const float*)d_in[7];
    const float* w1     = (const float*)d_in[8];
    const float* b1     = (const float*)d_in[9];
    const float* ln2_g  = (const float*)d_in[10];
    const float* ln2_b  = (const float*)d_in[11];
    const float* w2     = (const float*)d_in[12];
    const float* b2     = (const float*)d_in[13];
    float* out = (float*)d_out;

    // dynamic smem: A(hi+lo) + B(hi+lo) + bias + sw + si
    const int smem2 = 2 * 64 * CIN  * 2 + 2 * 192 * 64 * 2 + 768 + 768 + 768;  // 149760
    const int smem1 = 2 * 64 * COUT * 2 + 2 * 192 * 64 * 2 + 768 + 768 + 768;  // 100608
    cudaFuncSetAttribute(k_ln_gemm_mma<CIN,  false>,
                         cudaFuncAttributeMaxDynamicSharedMemorySize, smem2);
    cudaFuncSetAttribute(k_ln_gemm_mma<COUT, true>,
                         cudaFuncAttributeMaxDynamicSharedMemorySize, smem1);

    k_prep_w<<<(CIN  * COUT + 255) / 256, 256>>>(w2, CIN,  0);
    k_prep_w<<<(COUT * COUT + 255) / 256, 256>>>(w1, COUT, 1);
    k_grid_zero<<<2, 1024>>>();
    k_grid_count<<<NTOT / 256, 256>>>(xyz);
    k_grid_scan<<<1, 1024>>>();

    // branch 2: LN + GEMM (HMMA bf16 split)
    k_ln_gemm_mma<CIN, false><<<NTOT / 64, 256, smem2>>>(
        feats, ln2_g, ln2_b, b2, nullptr);

    k_grid_scatter<<<NTOT / 256, 256>>>(xyz);
    k_knn_grid<<<MTOT / 256, 256>>>(sxyz);

    // branch 1: LN + GEMM + fused gather
    k_ln_gemm_mma<COUT, true><<<MTOT / 64, 256, smem1>>>(
        sfeats, ln1_g, ln1_b, b1, out);

    const long long main_sz = (long long)MTOT * COUT;
    if ((long long)out_size > main_sz) {
        const long long extra = (long long)out_size - main_sz;
        if (extra >= (long long)MTOT * 3 + NB) {
            const int n = MTOT * 3 / 4 + NB;
            k_tail_fast<<<(n + 255) / 256, 256>>>(sxyz, soff, out);
        } else {
            k_tail_scalar<<<((int)extra + 255) / 256, 256>>>(sxyz, soff, out, (int)extra);
        }
    }
}